// round 11
// baseline (speedup 1.0000x reference)
#include <cuda_runtime.h>
#include <cuda_bf16.h>
#include <cstdint>

#define N_NODES 100000
#define N_EDGES 1600000
#define C 128

// ---------------- static scratch ----------------
__device__ float g_ni  [(size_t)N_NODES * C];
__device__ float g_h   [(size_t)N_NODES * C];   // u (fp32)
__device__ float g_g   [(size_t)N_NODES * C];   // v = agg(u)
__device__ float g_pre [(size_t)N_NODES * C];   // ni @ WdA + bd
__device__ float g_pref[(size_t)N_NODES * C];   // ni @ Wf1A + bf1
__device__ __nv_bfloat16 g_ubf[(size_t)N_NODES * C];   // bf16 copy of u for gather
__device__ float g_dis[N_NODES];
__device__ int   g_deg[N_NODES];
__device__ int   g_rowptr[N_NODES];
__device__ int   g_cursor[N_NODES];
__device__ int   g_csrsrc[N_EDGES];
__device__ int   g_total;

// bf16 hi/lo weights [k][n]
__device__ __nv_bfloat16 g_whi[90112];
__device__ __nv_bfloat16 g_wlo[90112];

#define SLOT_WG   0
#define SLOT_WDA  16384
#define SLOT_WDB  32768
#define SLOT_WF1A 49152
#define SLOT_WF1B 65536
#define SLOT_W1   81920
#define SLOT_W2   86016

// ---------------- PTX helpers ----------------
__device__ __forceinline__ uint32_t smem_u32(const void* p) {
    uint32_t a;
    asm("{ .reg .u64 t; cvta.to.shared.u64 t, %1; cvt.u32.u64 %0, t; }" : "=r"(a) : "l"(p));
    return a;
}
#define LDSM_X4(r, addr) \
    asm volatile("ldmatrix.sync.aligned.m8n8.x4.shared.b16 {%0,%1,%2,%3}, [%4];" \
        : "=r"((r)[0]), "=r"((r)[1]), "=r"((r)[2]), "=r"((r)[3]) : "r"(addr))
#define LDSM_X4T(r, addr) \
    asm volatile("ldmatrix.sync.aligned.m8n8.x4.trans.shared.b16 {%0,%1,%2,%3}, [%4];" \
        : "=r"((r)[0]), "=r"((r)[1]), "=r"((r)[2]), "=r"((r)[3]) : "r"(addr))
__device__ __forceinline__ void mma_bf16(float* c, const uint32_t* a, const uint32_t* b) {
    asm volatile("mma.sync.aligned.m16n8k16.row.col.f32.bf16.bf16.f32 "
        "{%0,%1,%2,%3}, {%4,%5,%6,%7}, {%8,%9}, {%0,%1,%2,%3};"
        : "+f"(c[0]), "+f"(c[1]), "+f"(c[2]), "+f"(c[3])
        : "r"(a[0]), "r"(a[1]), "r"(a[2]), "r"(a[3]), "r"(b[0]), "r"(b[1]));
}

// ---------------- init: weight split + node zeroing ----------------
__global__ void k_init(const float* __restrict__ Wg, const float* __restrict__ Wd,
                       const float* __restrict__ Wf1, const float* __restrict__ W1,
                       const float* __restrict__ W2) {
    int idx = blockIdx.x * blockDim.x + threadIdx.x;
    if (idx < 90112) {
        float v;
        if (idx < 16384)       v = Wg[idx];
        else if (idx < 49152)  v = Wd[idx - 16384];
        else if (idx < 81920)  v = Wf1[idx - 49152];
        else if (idx < 86016)  v = W1[idx - 81920];
        else                   v = W2[idx - 86016];
        __nv_bfloat16 h = __float2bfloat16(v);
        g_whi[idx] = h;
        g_wlo[idx] = __float2bfloat16(v - __bfloat162float(h));
    }
    if (idx < N_NODES) { g_deg[idx] = 0; g_cursor[idx] = 0; }
    if (idx == 0) g_total = 0;
}

__global__ void k_hist(const int* __restrict__ dst) {
    int e = blockIdx.x * blockDim.x + threadIdx.x;
    if (e < N_EDGES) atomicAdd(&g_deg[dst[e]], 1);
}

// atomic segment reservation replaces the prefix scan (segment order irrelevant)
__global__ void k_rowptr(void) {
    int i = blockIdx.x * blockDim.x + threadIdx.x;
    if (i < N_NODES) {
        int d = g_deg[i];
        g_rowptr[i] = atomicAdd(&g_total, d);
        g_dis[i] = rsqrtf((float)d + 1.0f);
    }
}

__global__ void k_fill(const int* __restrict__ src, const int* __restrict__ dst) {
    int e = blockIdx.x * blockDim.x + threadIdx.x;
    if (e < N_EDGES) {
        int d = dst[e];
        int pos = atomicAdd(&g_cursor[d], 1);
        g_csrsrc[g_rowptr[d] + pos] = src[e];
    }
}

// ---------------- GEMM building blocks ----------------
#define LDROW 272
#define TILE_A64  (64 * LDROW)    // 17408
#define TILE_W128 (128 * LDROW)   // 34816
#define TILE_W32  (32 * LDROW)

__device__ __forceinline__ void gemm_main64(uint32_t sb, int smA_h, int smA_l, int smB_h, int smB_l,
                                            int mw, int nw, int arow, int acb, int KC,
                                            float acc[2][4][4])
{
    #pragma unroll
    for (int kc = 0; kc < 8; kc++) {
        if (kc >= KC) break;
        int k0 = kc * 16;
        uint32_t ah[2][4], al[2][4], bh[2][4], bl[2][4];
        #pragma unroll
        for (int mt = 0; mt < 2; mt++) {
            uint32_t ra = (uint32_t)(mw + mt * 16 + arow) * LDROW + acb * 16 + k0 * 2;
            LDSM_X4(ah[mt], sb + smA_h + ra);
            LDSM_X4(al[mt], sb + smA_l + ra);
        }
        #pragma unroll
        for (int np = 0; np < 2; np++) {
            uint32_t rb = (uint32_t)(k0 + arow) * LDROW + (nw + np * 16 + acb * 8) * 2;
            LDSM_X4T(bh[np], sb + smB_h + rb);
            LDSM_X4T(bl[np], sb + smB_l + rb);
        }
        #pragma unroll
        for (int mt = 0; mt < 2; mt++)
            #pragma unroll
            for (int nt = 0; nt < 4; nt++) {
                mma_bf16(acc[mt][nt], ah[mt], &bh[nt >> 1][(nt & 1) * 2]);
                mma_bf16(acc[mt][nt], ah[mt], &bl[nt >> 1][(nt & 1) * 2]);
                mma_bf16(acc[mt][nt], al[mt], &bh[nt >> 1][(nt & 1) * 2]);
            }
    }
}

__device__ __forceinline__ void acc_zero2(float acc[2][4][4]) {
    #pragma unroll
    for (int i = 0; i < 2; i++)
        #pragma unroll
        for (int j = 0; j < 4; j++)
            #pragma unroll
            for (int e = 0; e < 4; e++) acc[i][j][e] = 0.f;
}

__device__ __forceinline__ void split2(float x, float y, __nv_bfloat162& h, __nv_bfloat162& l) {
    __nv_bfloat16 hx = __float2bfloat16(x), hy = __float2bfloat16(y);
    h = __nv_bfloat162(hx, hy);
    l = __nv_bfloat162(__float2bfloat16(x - __bfloat162float(hx)),
                       __float2bfloat16(y - __bfloat162float(hy)));
}

__device__ __forceinline__ void load_A_split64(char* smem, int smA_h, int smA_l,
                                               const float* __restrict__ A, int m0, int t)
{
    #pragma unroll
    for (int it = 0; it < 8; it++) {
        int idx = it * 256 + t;
        int row = idx >> 5;
        int seg = idx & 31;
        int grow = m0 + row;
        float4 v = make_float4(0.f, 0.f, 0.f, 0.f);
        if (grow < N_NODES) v = *(const float4*)&A[(size_t)grow * C + seg * 4];
        __nv_bfloat162 hA, lA, hB, lB;
        split2(v.x, v.y, hA, lA);
        split2(v.z, v.w, hB, lB);
        char* ph = smem + smA_h + row * LDROW + seg * 8;
        char* pl = smem + smA_l + row * LDROW + seg * 8;
        *(__nv_bfloat162*)(ph)     = hA;
        *(__nv_bfloat162*)(ph + 4) = hB;
        *(__nv_bfloat162*)(pl)     = lA;
        *(__nv_bfloat162*)(pl + 4) = lB;
    }
}

__device__ __forceinline__ void load_W128(char* smem, int dst, const __nv_bfloat16* __restrict__ W, int t)
{
    #pragma unroll
    for (int it = 0; it < 8; it++) {
        int idx = it * 256 + t;
        int row = idx >> 4;
        int seg = idx & 15;
        *(uint4*)(smem + dst + row * LDROW + seg * 16) = *(const uint4*)&W[row * 128 + seg * 8];
    }
}

#define SM_AH 0
#define SM_AL TILE_A64
#define SM_WH (2 * TILE_A64)
#define SM_WL (2 * TILE_A64 + TILE_W128)
#define SM_TOT (2 * TILE_A64 + 2 * TILE_W128)   // 104448 -> 2 CTAs/SM

// ---------------- dual prelude GEMM ----------------
__global__ void __launch_bounds__(256, 2) k_dual(
    const float* __restrict__ A,
    const float* __restrict__ bd, const float* __restrict__ bf1)
{
    extern __shared__ __align__(128) char smem[];
    uint32_t sb = smem_u32(smem);
    int t = threadIdx.x;
    int m0 = blockIdx.x * 64;

    load_A_split64(smem, SM_AH, SM_AL, A, m0, t);
    load_W128(smem, SM_WH, g_whi + SLOT_WDA, t);
    load_W128(smem, SM_WL, g_wlo + SLOT_WDA, t);
    __syncthreads();

    int wid = t >> 5, lane = t & 31;
    int mw = (wid & 1) * 32, nw = (wid >> 1) * 32;
    int arow = lane & 15, acb = lane >> 4;
    int gid = lane >> 2, t4 = lane & 3;

    float acc[2][4][4];
    acc_zero2(acc);
    gemm_main64(sb, SM_AH, SM_AL, SM_WH, SM_WL, mw, nw, arow, acb, 8, acc);
    __syncthreads();

    #pragma unroll
    for (int mt = 0; mt < 2; mt++) {
        int r0 = m0 + mw + mt * 16 + gid, r1 = r0 + 8;
        bool v0 = r0 < N_NODES, v1 = r1 < N_NODES;
        #pragma unroll
        for (int nt = 0; nt < 4; nt++) {
            int col = nw + nt * 8 + t4 * 2;
            float2 bb = *(const float2*)&bd[col];
            float* a = acc[mt][nt];
            if (v0) *(float2*)&g_pre[(size_t)r0 * C + col] = make_float2(a[0] + bb.x, a[1] + bb.y);
            if (v1) *(float2*)&g_pre[(size_t)r1 * C + col] = make_float2(a[2] + bb.x, a[3] + bb.y);
        }
    }
    load_W128(smem, SM_WH, g_whi + SLOT_WF1A, t);
    load_W128(smem, SM_WL, g_wlo + SLOT_WF1A, t);
    __syncthreads();

    acc_zero2(acc);
    gemm_main64(sb, SM_AH, SM_AL, SM_WH, SM_WL, mw, nw, arow, acb, 8, acc);

    #pragma unroll
    for (int mt = 0; mt < 2; mt++) {
        int r0 = m0 + mw + mt * 16 + gid, r1 = r0 + 8;
        bool v0 = r0 < N_NODES, v1 = r1 < N_NODES;
        #pragma unroll
        for (int nt = 0; nt < 4; nt++) {
            int col = nw + nt * 8 + t4 * 2;
            float2 bb = *(const float2*)&bf1[col];
            float* a = acc[mt][nt];
            if (v0) *(float2*)&g_pref[(size_t)r0 * C + col] = make_float2(a[0] + bb.x, a[1] + bb.y);
            if (v1) *(float2*)&g_pref[(size_t)r1 * C + col] = make_float2(a[2] + bb.x, a[3] + bb.y);
        }
    }
}

// ---------------- layer: GEMM1(Wg)+epi1 -> reload W -> GEMM2(WdB)+epi2 ----------------
template<bool LAST>
__global__ void __launch_bounds__(256, 2) k_layer(
    const float* __restrict__ V, const float* __restrict__ bg,
    const float* __restrict__ P, float* __restrict__ out)
{
    extern __shared__ __align__(128) char smem[];
    uint32_t sb = smem_u32(smem);
    int t = threadIdx.x;
    int m0 = blockIdx.x * 64;

    load_A_split64(smem, SM_AH, SM_AL, V, m0, t);
    load_W128(smem, SM_WH, g_whi + SLOT_WG, t);
    load_W128(smem, SM_WL, g_wlo + SLOT_WG, t);
    __syncthreads();

    int wid = t >> 5, lane = t & 31;
    int mw = (wid & 1) * 32, nw = (wid >> 1) * 32;
    int arow = lane & 15, acb = lane >> 4;
    int gid = lane >> 2, t4 = lane & 3;

    float acc[2][4][4];
    acc_zero2(acc);
    gemm_main64(sb, SM_AH, SM_AL, SM_WH, SM_WL, mw, nw, arow, acb, 8, acc);
    __syncthreads();

    #pragma unroll
    for (int mt = 0; mt < 2; mt++) {
        int lr0 = mw + mt * 16 + gid, lr1 = lr0 + 8;
        int gr0 = m0 + lr0, gr1 = m0 + lr1;
        float d0 = (gr0 < N_NODES) ? g_dis[gr0] : 0.f;
        float d1 = (gr1 < N_NODES) ? g_dis[gr1] : 0.f;
        #pragma unroll
        for (int nt = 0; nt < 4; nt++) {
            int col = nw + nt * 8 + t4 * 2;
            float2 bb = *(const float2*)&bg[col];
            float* a = acc[mt][nt];
            float g00 = fmaxf(fmaf(a[0], d0, bb.x), 0.f);
            float g01 = fmaxf(fmaf(a[1], d0, bb.y), 0.f);
            float g10 = fmaxf(fmaf(a[2], d1, bb.x), 0.f);
            float g11 = fmaxf(fmaf(a[3], d1, bb.y), 0.f);
            __nv_bfloat162 h0v, l0v, h1v, l1v;
            split2(g00, g01, h0v, l0v);
            split2(g10, g11, h1v, l1v);
            *(__nv_bfloat162*)(smem + SM_AH + lr0 * LDROW + col * 2) = h0v;
            *(__nv_bfloat162*)(smem + SM_AL + lr0 * LDROW + col * 2) = l0v;
            *(__nv_bfloat162*)(smem + SM_AH + lr1 * LDROW + col * 2) = h1v;
            *(__nv_bfloat162*)(smem + SM_AL + lr1 * LDROW + col * 2) = l1v;
        }
    }
    load_W128(smem, SM_WH, g_whi + SLOT_WDB, t);
    load_W128(smem, SM_WL, g_wlo + SLOT_WDB, t);
    __syncthreads();

    acc_zero2(acc);
    gemm_main64(sb, SM_AH, SM_AL, SM_WH, SM_WL, mw, nw, arow, acb, 8, acc);

    #pragma unroll
    for (int mt = 0; mt < 2; mt++) {
        int gr0 = m0 + mw + mt * 16 + gid, gr1 = gr0 + 8;
        bool v0 = gr0 < N_NODES, v1 = gr1 < N_NODES;
        float d0 = 1.f, d1 = 1.f;
        if (!LAST) {
            if (v0) d0 = g_dis[gr0];
            if (v1) d1 = g_dis[gr1];
        }
        #pragma unroll
        for (int nt = 0; nt < 4; nt++) {
            int col = nw + nt * 8 + t4 * 2;
            float* a = acc[mt][nt];
            if (v0) {
                float2 p = *(const float2*)&P[(size_t)gr0 * C + col];
                float2 r = make_float2(fmaxf(a[0] + p.x, 0.f) * d0, fmaxf(a[1] + p.y, 0.f) * d0);
                *(float2*)&out[(size_t)gr0 * C + col] = r;
                if (!LAST)
                    *(__nv_bfloat162*)&g_ubf[(size_t)gr0 * C + col] = __float22bfloat162_rn(r);
            }
            if (v1) {
                float2 p = *(const float2*)&P[(size_t)gr1 * C + col];
                float2 r = make_float2(fmaxf(a[2] + p.x, 0.f) * d1, fmaxf(a[3] + p.y, 0.f) * d1);
                *(float2*)&out[(size_t)gr1 * C + col] = r;
                if (!LAST)
                    *(__nv_bfloat162*)&g_ubf[(size_t)gr1 * C + col] = __float22bfloat162_rn(r);
            }
        }
    }
}

// ---------------- final: h2 = relu(u@Wf1B + pref) [smem]; out = h2@Wf2 + bf2 ----------------
__global__ void __launch_bounds__(256, 2) k_final(
    const float* __restrict__ U, const float* __restrict__ P,
    const float* __restrict__ Wf2, const float* __restrict__ bf2,
    float* __restrict__ out)
{
    extern __shared__ __align__(128) char smem[];
    uint32_t sb = smem_u32(smem);
    int t = threadIdx.x;
    int m0 = blockIdx.x * 64;

    load_A_split64(smem, SM_AH, SM_AL, U, m0, t);
    load_W128(smem, SM_WH, g_whi + SLOT_WF1B, t);
    load_W128(smem, SM_WL, g_wlo + SLOT_WF1B, t);
    __syncthreads();

    int wid = t >> 5, lane = t & 31;
    int mw = (wid & 1) * 32, nw = (wid >> 1) * 32;
    int arow = lane & 15, acb = lane >> 4;
    int gid = lane >> 2, t4 = lane & 3;

    float acc[2][4][4];
    acc_zero2(acc);
    gemm_main64(sb, SM_AH, SM_AL, SM_WH, SM_WL, mw, nw, arow, acb, 8, acc);
    __syncthreads();

    float* h2s = (float*)(smem + SM_AH);
    #pragma unroll
    for (int mt = 0; mt < 2; mt++) {
        int lr0 = mw + mt * 16 + gid, lr1 = lr0 + 8;
        int gr0 = m0 + lr0, gr1 = m0 + lr1;
        #pragma unroll
        for (int nt = 0; nt < 4; nt++) {
            int col = nw + nt * 8 + t4 * 2;
            float* a = acc[mt][nt];
            float2 p0 = (gr0 < N_NODES) ? *(const float2*)&P[(size_t)gr0 * C + col] : make_float2(0.f, 0.f);
            float2 p1 = (gr1 < N_NODES) ? *(const float2*)&P[(size_t)gr1 * C + col] : make_float2(0.f, 0.f);
            *(float2*)&h2s[lr0 * C + col] = make_float2(fmaxf(a[0] + p0.x, 0.f), fmaxf(a[1] + p0.y, 0.f));
            *(float2*)&h2s[lr1 * C + col] = make_float2(fmaxf(a[2] + p1.x, 0.f), fmaxf(a[3] + p1.y, 0.f));
        }
    }
    __syncthreads();

    float4 w01 = *(const float4*)&Wf2[lane * 8];
    float4 w23 = *(const float4*)&Wf2[lane * 8 + 4];
    float bb0 = bf2[0], bb1 = bf2[1];
    for (int i = 0; i < 8; i++) {
        int lr = wid * 8 + i;
        int n = m0 + lr;
        if (n >= N_NODES) break;
        float4 h = *(const float4*)&h2s[lr * C + lane * 4];
        float s0 = h.x * w01.x + h.y * w01.z + h.z * w23.x + h.w * w23.z;
        float s1 = h.x * w01.y + h.y * w01.w + h.z * w23.y + h.w * w23.w;
        #pragma unroll
        for (int off = 16; off > 0; off >>= 1) {
            s0 += __shfl_xor_sync(0xFFFFFFFF, s0, off);
            s1 += __shfl_xor_sync(0xFFFFFFFF, s1, off);
        }
        if (lane == 0) {
            out[(size_t)n * 2 + 0] = s0 + bb0;
            out[(size_t)n * 2 + 1] = s1 + bb1;
        }
    }
}

// ---------------- preproc (HMMA) ----------------
#define SP_AH 0
#define SP_AL (SP_AH + TILE_W128)
#define SP_W1H (SP_AL + TILE_W128)
#define SP_W1L (SP_W1H + TILE_W32)
#define SP_W2H (SP_W1L + TILE_W32)
#define SP_W2L (SP_W2H + TILE_W32)
#define SP_TOT (SP_W2L + TILE_W32)      // 104448

__global__ void __launch_bounds__(256, 2) k_pre2(
    const float* __restrict__ x,
    const float* __restrict__ Wp, const float* __restrict__ bp,
    const float* __restrict__ b1, const float* __restrict__ b2,
    float* __restrict__ ubuf)
{
    extern __shared__ __align__(128) char smem[];
    __shared__ float sWp[8 * 32];
    __shared__ float sbp[32];
    __shared__ float xs[128][8];
    uint32_t sb = smem_u32(smem);
    int t = threadIdx.x;
    int m0 = blockIdx.x * 128;

    if (t < 256) sWp[t] = Wp[t];
    if (t < 32) sbp[t] = bp[t];
    #pragma unroll
    for (int it = 0; it < 4; it++) {
        int idx = it * 256 + t;
        int row = idx >> 3, f = idx & 7;
        int grow = m0 + row;
        xs[row][f] = (grow < N_NODES) ? x[(size_t)grow * 8 + f] : 0.f;
    }
    #pragma unroll
    for (int it = 0; it < 2; it++) {
        int idx = it * 256 + t;
        int row = idx >> 4, seg = idx & 15;
        *(uint4*)(smem + SP_W1H + row * LDROW + seg * 16) = *(const uint4*)&g_whi[SLOT_W1 + row * 128 + seg * 8];
        *(uint4*)(smem + SP_W1L + row * LDROW + seg * 16) = *(const uint4*)&g_wlo[SLOT_W1 + row * 128 + seg * 8];
        *(uint4*)(smem + SP_W2H + row * LDROW + seg * 16) = *(const uint4*)&g_whi[SLOT_W2 + row * 128 + seg * 8];
        *(uint4*)(smem + SP_W2L + row * LDROW + seg * 16) = *(const uint4*)&g_wlo[SLOT_W2 + row * 128 + seg * 8];
    }
    __syncthreads();

    #pragma unroll
    for (int it = 0; it < 16; it++) {
        int idx = it * 256 + t;
        int row = idx >> 5, k = idx & 31;
        float s = sbp[k];
        #pragma unroll
        for (int f = 0; f < 8; f++) s = fmaf(xs[row][f], sWp[f * 32 + k], s);
        __nv_bfloat16 h = __float2bfloat16(s);
        *(__nv_bfloat16*)(smem + SP_AH + row * LDROW + k * 2) = h;
        *(__nv_bfloat16*)(smem + SP_AL + row * LDROW + k * 2) =
            __float2bfloat16(s - __bfloat162float(h));
    }
    __syncthreads();

    int wid = t >> 5, lane = t & 31;
    int mw = (wid & 1) * 64, nw = (wid >> 1) * 32;
    int arow = lane & 15, acb = lane >> 4;
    int gid = lane >> 2, t4 = lane & 3;

    float acc[2][4][4];

    #pragma unroll
    for (int half = 0; half < 2; half++) {
        acc_zero2(acc);
        gemm_main64(sb, SP_AH, SP_AL, SP_W1H, SP_W1L, mw + half * 32, nw, arow, acb, 2, acc);
        #pragma unroll
        for (int mt = 0; mt < 2; mt++) {
            int r0 = m0 + mw + half * 32 + mt * 16 + gid, r1 = r0 + 8;
            bool v0 = r0 < N_NODES, v1 = r1 < N_NODES;
            #pragma unroll
            for (int nt = 0; nt < 4; nt++) {
                int col = nw + nt * 8 + t4 * 2;
                float2 bb = *(const float2*)&b1[col];
                float* a = acc[mt][nt];
                if (v0) *(float2*)&g_ni[(size_t)r0 * C + col] =
                    make_float2(fmaxf(a[0] + bb.x, 0.f), fmaxf(a[1] + bb.y, 0.f));
                if (v1) *(float2*)&g_ni[(size_t)r1 * C + col] =
                    make_float2(fmaxf(a[2] + bb.x, 0.f), fmaxf(a[3] + bb.y, 0.f));
            }
        }
    }

    #pragma unroll
    for (int half = 0; half < 2; half++) {
        acc_zero2(acc);
        gemm_main64(sb, SP_AH, SP_AL, SP_W2H, SP_W2L, mw + half * 32, nw, arow, acb, 2, acc);
        #pragma unroll
        for (int mt = 0; mt < 2; mt++) {
            int r0 = m0 + mw + half * 32 + mt * 16 + gid, r1 = r0 + 8;
            bool v0 = r0 < N_NODES, v1 = r1 < N_NODES;
            float d0 = v0 ? g_dis[r0] : 0.f;
            float d1 = v1 ? g_dis[r1] : 0.f;
            #pragma unroll
            for (int nt = 0; nt < 4; nt++) {
                int col = nw + nt * 8 + t4 * 2;
                float2 bb = *(const float2*)&b2[col];
                float* a = acc[mt][nt];
                if (v0) {
                    float2 r = make_float2(fmaxf(a[0] + bb.x, 0.f) * d0, fmaxf(a[1] + bb.y, 0.f) * d0);
                    *(float2*)&ubuf[(size_t)r0 * C + col] = r;
                    *(__nv_bfloat162*)&g_ubf[(size_t)r0 * C + col] = __float22bfloat162_rn(r);
                }
                if (v1) {
                    float2 r = make_float2(fmaxf(a[2] + bb.x, 0.f) * d1, fmaxf(a[3] + bb.y, 0.f) * d1);
                    *(float2*)&ubuf[(size_t)r1 * C + col] = r;
                    *(__nv_bfloat162*)&g_ubf[(size_t)r1 * C + col] = __float22bfloat162_rn(r);
                }
            }
        }
    }
}

// ---------------- aggregation: v[n] = u[n](fp32) + sum ubf[j](bf16) ----------------
// two neighbors per warp: lanes 0-15 handle neighbor j, lanes 16-31 neighbor j+1.
// each lane loads uint4 = 8 bf16 channels: channels (lane&15)*8 .. +7
__global__ void __launch_bounds__(256) k_agg(const float* __restrict__ U, float* __restrict__ Vout) {
    int gt = blockIdx.x * blockDim.x + threadIdx.x;
    int w = gt >> 5;
    if (w >= N_NODES) return;
    int lane = threadIdx.x & 31;
    int li = lane & 15;
    int half = lane >> 4;

    int base = g_rowptr[w];
    int deg  = g_deg[w];

    float acc[8];
    if (half == 0) {
        float4 a = *(const float4*)&U[(size_t)w * C + li * 8];
        float4 b = *(const float4*)&U[(size_t)w * C + li * 8 + 4];
        acc[0] = a.x; acc[1] = a.y; acc[2] = a.z; acc[3] = a.w;
        acc[4] = b.x; acc[5] = b.y; acc[6] = b.z; acc[7] = b.w;
    } else {
        #pragma unroll
        for (int i = 0; i < 8; i++) acc[i] = 0.f;
    }

    const __nv_bfloat16* ubf = g_ubf;
    int j = 0;
    for (; j + 4 <= deg; j += 4) {
        int sA = g_csrsrc[base + j + half];
        int sB = g_csrsrc[base + j + 2 + half];
        uint4 dA = *(const uint4*)(ubf + (size_t)sA * C + li * 8);
        uint4 dB = *(const uint4*)(ubf + (size_t)sB * C + li * 8);
        float2 a0 = __bfloat1622float2(*(__nv_bfloat162*)&dA.x);
        float2 a1 = __bfloat1622float2(*(__nv_bfloat162*)&dA.y);
        float2 a2 = __bfloat1622float2(*(__nv_bfloat162*)&dA.z);
        float2 a3 = __bfloat1622float2(*(__nv_bfloat162*)&dA.w);
        float2 b0 = __bfloat1622float2(*(__nv_bfloat162*)&dB.x);
        float2 b1 = __bfloat1622float2(*(__nv_bfloat162*)&dB.y);
        float2 b2 = __bfloat1622float2(*(__nv_bfloat162*)&dB.z);
        float2 b3 = __bfloat1622float2(*(__nv_bfloat162*)&dB.w);
        acc[0] += a0.x + b0.x; acc[1] += a0.y + b0.y;
        acc[2] += a1.x + b1.x; acc[3] += a1.y + b1.y;
        acc[4] += a2.x + b2.x; acc[5] += a2.y + b2.y;
        acc[6] += a3.x + b3.x; acc[7] += a3.y + b3.y;
    }
    if (j + 2 <= deg) {
        int s = g_csrsrc[base + j + half];
        uint4 d = *(const uint4*)(ubf + (size_t)s * C + li * 8);
        float2 p0 = __bfloat1622float2(*(__nv_bfloat162*)&d.x);
        float2 p1 = __bfloat1622float2(*(__nv_bfloat162*)&d.y);
        float2 p2 = __bfloat1622float2(*(__nv_bfloat162*)&d.z);
        float2 p3 = __bfloat1622float2(*(__nv_bfloat162*)&d.w);
        acc[0] += p0.x; acc[1] += p0.y; acc[2] += p1.x; acc[3] += p1.y;
        acc[4] += p2.x; acc[5] += p2.y; acc[6] += p3.x; acc[7] += p3.y;
        j += 2;
    }
    if (j < deg && half == 0) {
        int s = g_csrsrc[base + j];
        uint4 d = *(const uint4*)(ubf + (size_t)s * C + li * 8);
        float2 p0 = __bfloat1622float2(*(__nv_bfloat162*)&d.x);
        float2 p1 = __bfloat1622float2(*(__nv_bfloat162*)&d.y);
        float2 p2 = __bfloat1622float2(*(__nv_bfloat162*)&d.z);
        float2 p3 = __bfloat1622float2(*(__nv_bfloat162*)&d.w);
        acc[0] += p0.x; acc[1] += p0.y; acc[2] += p1.x; acc[3] += p1.y;
        acc[4] += p2.x; acc[5] += p2.y; acc[6] += p3.x; acc[7] += p3.y;
    }

    // combine halves
    #pragma unroll
    for (int i = 0; i < 8; i++) acc[i] += __shfl_xor_sync(0xFFFFFFFF, acc[i], 16);

    // write: half 0 writes channels li*8..+3, half 1 writes li*8+4..+7
    float* vp = &Vout[(size_t)w * C + li * 8 + half * 4];
    *(float4*)vp = make_float4(acc[half * 4 + 0], acc[half * 4 + 1],
                               acc[half * 4 + 2], acc[half * 4 + 3]);
}

// ---------------- host launcher ----------------
extern "C" void kernel_launch(void* const* d_in, const int* in_sizes, int n_in,
                              void* d_out, int out_size)
{
    const float* x   = (const float*)d_in[0];
    const int* ei    = (const int*)d_in[1];
    const float* Wp  = (const float*)d_in[2];
    const float* bp  = (const float*)d_in[3];
    const float* W1  = (const float*)d_in[4];
    const float* b1  = (const float*)d_in[5];
    const float* W2  = (const float*)d_in[6];
    const float* b2  = (const float*)d_in[7];
    const float* Wg  = (const float*)d_in[8];
    const float* bg  = (const float*)d_in[9];
    const float* Wd  = (const float*)d_in[10];
    const float* bd  = (const float*)d_in[11];
    const float* Wf1 = (const float*)d_in[12];
    const float* bf1 = (const float*)d_in[13];
    const float* Wf2 = (const float*)d_in[14];
    const float* bf2 = (const float*)d_in[15];
    float* out = (float*)d_out;

    const int* src = ei;
    const int* dst = ei + N_EDGES;

    float* d_ni = nullptr;   cudaGetSymbolAddress((void**)&d_ni,   g_ni);
    float* d_u  = nullptr;   cudaGetSymbolAddress((void**)&d_u,    g_h);
    float* d_v  = nullptr;   cudaGetSymbolAddress((void**)&d_v,    g_g);
    float* d_pre = nullptr;  cudaGetSymbolAddress((void**)&d_pre,  g_pre);
    float* d_pref = nullptr; cudaGetSymbolAddress((void**)&d_pref, g_pref);

    cudaFuncSetAttribute(k_dual, cudaFuncAttributeMaxDynamicSharedMemorySize, SM_TOT);
    cudaFuncSetAttribute(k_layer<false>, cudaFuncAttributeMaxDynamicSharedMemorySize, SM_TOT);
    cudaFuncSetAttribute(k_layer<true>,  cudaFuncAttributeMaxDynamicSharedMemorySize, SM_TOT);
    cudaFuncSetAttribute(k_final, cudaFuncAttributeMaxDynamicSharedMemorySize, SM_TOT);
    cudaFuncSetAttribute(k_pre2, cudaFuncAttributeMaxDynamicSharedMemorySize, SP_TOT);

    const int MB64  = (N_NODES + 63) / 64;        // 1563
    const int MB128 = (N_NODES + 127) / 128;      // 782
    const int WPB = (N_NODES * 32 + 255) / 256;   // 12500

    // launch order arranged so launch #6 (ncu -s 5 -c 1) is the first real k_agg
    k_init<<<(N_NODES + 255) / 256, 256>>>(Wg, Wd, Wf1, W1, W2);           // 1
    k_hist<<<(N_EDGES + 255) / 256, 256>>>(dst);                           // 2
    k_rowptr<<<(N_NODES + 255) / 256, 256>>>();                            // 3
    k_fill<<<(N_EDGES + 255) / 256, 256>>>(src, dst);                      // 4
    k_pre2<<<MB128, 256, SP_TOT>>>(x, Wp, bp, b1, b2, d_u);                // 5
    k_agg<<<WPB, 256>>>(d_u, d_v);                                         // 6 <- ncu capture
    k_dual<<<MB64, 256, SM_TOT>>>(d_ni, bd, bf1);                          // 7
    k_layer<false><<<MB64, 256, SM_TOT>>>(d_v, bg, d_pre, d_u);            // 8 (layer 0)

    for (int l = 1; l < 8; l++) {
        k_agg<<<WPB, 256>>>(d_u, d_v);
        if (l < 7) k_layer<false><<<MB64, 256, SM_TOT>>>(d_v, bg, d_pre, d_u);
        else       k_layer<true ><<<MB64, 256, SM_TOT>>>(d_v, bg, d_pre, d_u);
    }

    k_final<<<MB64, 256, SM_TOT>>>(d_u, d_pref, Wf2, bf2, out);
}